// round 13
// baseline (speedup 1.0000x reference)
#include <cuda_runtime.h>
#include <cuda_bf16.h>
#include <cstdint>

// ---------------------------------------------------------------------------
// Spiking attention, B=4, N=1024, C=512, H=8, hd=64.
//   1) qkv = spike(x) @ Wqkv^T      tf32 HMMA, W split hi/lo (~fp32 accurate)
//   2) BN stats
//   3) s_qkv = spike(BN(qkv)) -> bf16 (exact integers {0..4})
//   4) attention: bf16 HMMA (m16n8k16), exact integer arithmetic
//   5) final = out_s @ Wproj^T + b  tf32 HMMA, W split hi/lo
// ---------------------------------------------------------------------------

#define B_  4
#define N_  1024
#define C_  512
#define H_  8
#define HD_ 64
#define M_  (B_ * N_)      // 4096
#define C3_ (3 * C_)       // 1536

__device__ __forceinline__ float spikef(float x) {
    x = fminf(fmaxf(x, 0.0f), 4.0f);
    return floorf(x + 0.5f);
}

// ---- scratch (allocation-free: device globals) ----
__device__ float          g_qkv [M_ * C3_];
__device__ __nv_bfloat16  g_sqkv[M_ * C3_];
__device__ float          g_mu  [C3_];
__device__ float          g_rstd[C3_];
__device__ float          g_outs[M_ * C_];

// ===========================================================================
// helpers
// ===========================================================================
__device__ __forceinline__ uint32_t smem_u32(const void* p) {
    uint32_t a;
    asm("{ .reg .u64 t; cvta.to.shared.u64 t, %1; cvt.u32.u64 %0, t; }" : "=r"(a) : "l"(p));
    return a;
}
__device__ __forceinline__ uint32_t f2tf32(float f) {
    uint32_t u;
    asm("cvt.rna.tf32.f32 %0, %1;" : "=r"(u) : "f"(f));
    return u;
}
__device__ __forceinline__ void ldsm_x4(uint32_t addr, uint32_t r[4]) {
    asm volatile("ldmatrix.sync.aligned.m8n8.x4.shared.b16 {%0,%1,%2,%3}, [%4];"
                 : "=r"(r[0]), "=r"(r[1]), "=r"(r[2]), "=r"(r[3]) : "r"(addr));
}
__device__ __forceinline__ void ldsm_x4_t(uint32_t addr, uint32_t r[4]) {
    asm volatile("ldmatrix.sync.aligned.m8n8.x4.trans.shared.b16 {%0,%1,%2,%3}, [%4];"
                 : "=r"(r[0]), "=r"(r[1]), "=r"(r[2]), "=r"(r[3]) : "r"(addr));
}
__device__ __forceinline__ void mma_bf16(float c[4], const uint32_t a[4],
                                         uint32_t b0, uint32_t b1) {
    asm volatile("mma.sync.aligned.m16n8k16.row.col.f32.bf16.bf16.f32 "
                 "{%0,%1,%2,%3}, {%4,%5,%6,%7}, {%8,%9}, {%0,%1,%2,%3};"
                 : "+f"(c[0]), "+f"(c[1]), "+f"(c[2]), "+f"(c[3])
                 : "r"(a[0]), "r"(a[1]), "r"(a[2]), "r"(a[3]), "r"(b0), "r"(b1));
}
__device__ __forceinline__ void mma_tf32(float c[4], const uint32_t a[4],
                                         uint32_t b0, uint32_t b1) {
    asm volatile("mma.sync.aligned.m16n8k8.row.col.f32.tf32.tf32.f32 "
                 "{%0,%1,%2,%3}, {%4,%5,%6,%7}, {%8,%9}, {%0,%1,%2,%3};"
                 : "+f"(c[0]), "+f"(c[1]), "+f"(c[2]), "+f"(c[3])
                 : "r"(a[0]), "r"(a[1]), "r"(a[2]), "r"(a[3]), "r"(b0), "r"(b1));
}
__device__ __forceinline__ uint32_t pack_bf16x2(float lo, float hi) {
    uint32_t r;
    asm("cvt.rn.bf16x2.f32 %0, %1, %2;" : "=r"(r) : "f"(hi), "f"(lo));
    return r;
}

// ===========================================================================
// tf32 GEMM with split-W: C[M,N] = cvt(op(A))[M,K] @ (Whi+Wlo)[N,K]^T (+bias)
// 256 threads, tile 128m x 128n, BK=32; warps: 2m x 4n, each 64m x 32n.
// SMEM stride 36 words -> conflict-free fragment lds.
// ===========================================================================
#define GEMM_SMEM (3 * 4608 * 4)   // As, Bhi, Blo: each 128*36 u32

template<bool SPIKE_A, bool HAS_BIAS>
__global__ void __launch_bounds__(256)
gemm_tf32(const float* __restrict__ A, const float* __restrict__ W,
          const float* __restrict__ bias, float* __restrict__ Cm,
          int M, int N, int K) {
    extern __shared__ uint32_t smu[];
    uint32_t* As = smu;           // [128][36]
    uint32_t* Bh = smu + 4608;
    uint32_t* Bl = smu + 9216;
    const int m0 = blockIdx.y * 128;
    const int n0 = blockIdx.x * 128;
    const int tid = threadIdx.x;
    const int wid = tid >> 5, L = tid & 31;
    const int mb = (wid >> 2) * 64;      // warp m base (0/64)
    const int nb = (wid & 3) * 32;       // warp n base
    const int lr = L >> 2, lc = L & 3;

    float c[4][4][4] = {};               // [mtile][ntile][frag]

    for (int k0 = 0; k0 < K; k0 += 32) {
        #pragma unroll
        for (int u = 0; u < 4; u++) {
            int idx = tid + u * 256;     // float4 slot 0..1023
            int r = idx >> 3;
            int cc = (idx & 7) * 4;
            float4 v = *(const float4*)(A + (size_t)(m0 + r) * K + k0 + cc);
            if (SPIKE_A) { v.x = spikef(v.x); v.y = spikef(v.y); v.z = spikef(v.z); v.w = spikef(v.w); }
            uint4 o = { f2tf32(v.x), f2tf32(v.y), f2tf32(v.z), f2tf32(v.w) };
            *(uint4*)(As + r * 36 + cc) = o;

            float4 w = *(const float4*)(W + (size_t)(n0 + r) * K + k0 + cc);
            uint4 hi, lo;
            hi.x = f2tf32(w.x); lo.x = f2tf32(w.x - __uint_as_float(hi.x));
            hi.y = f2tf32(w.y); lo.y = f2tf32(w.y - __uint_as_float(hi.y));
            hi.z = f2tf32(w.z); lo.z = f2tf32(w.z - __uint_as_float(hi.z));
            hi.w = f2tf32(w.w); lo.w = f2tf32(w.w - __uint_as_float(hi.w));
            *(uint4*)(Bh + r * 36 + cc) = hi;
            *(uint4*)(Bl + r * 36 + cc) = lo;
        }
        __syncthreads();

        #pragma unroll
        for (int kk = 0; kk < 4; kk++) {
            const int co = kk * 8 + lc;
            uint32_t af[4][4];
            #pragma unroll
            for (int i = 0; i < 4; i++) {
                const int r = mb + 16 * i + lr;
                af[i][0] = As[r * 36 + co];
                af[i][1] = As[(r + 8) * 36 + co];
                af[i][2] = As[r * 36 + co + 4];
                af[i][3] = As[(r + 8) * 36 + co + 4];
            }
            #pragma unroll
            for (int t = 0; t < 4; t++) {
                const int rn = nb + 8 * t + lr;
                uint32_t bh0 = Bh[rn * 36 + co], bh1 = Bh[rn * 36 + co + 4];
                uint32_t bl0 = Bl[rn * 36 + co], bl1 = Bl[rn * 36 + co + 4];
                #pragma unroll
                for (int i = 0; i < 4; i++) {
                    mma_tf32(c[i][t], af[i], bh0, bh1);
                    mma_tf32(c[i][t], af[i], bl0, bl1);
                }
            }
        }
        __syncthreads();
    }

    #pragma unroll
    for (int i = 0; i < 4; i++) {
        #pragma unroll
        for (int t = 0; t < 4; t++) {
            const int row = m0 + mb + 16 * i + lr;
            const int col = n0 + nb + 8 * t + 2 * lc;
            float b0 = 0.f, b1 = 0.f;
            if (HAS_BIAS) { b0 = bias[col]; b1 = bias[col + 1]; }
            float2 v0 = { c[i][t][0] + b0, c[i][t][1] + b1 };
            float2 v1 = { c[i][t][2] + b0, c[i][t][3] + b1 };
            *(float2*)(Cm + (size_t)row * N + col)       = v0;
            *(float2*)(Cm + (size_t)(row + 8) * N + col) = v1;
        }
    }
}

// ===========================================================================
__global__ void bn_stats(const float* __restrict__ qkv) {
    __shared__ float ssum[256], ssq[256];
    const int j0 = blockIdx.x * 32;
    const int jl = threadIdx.x & 31;
    const int rh = threadIdx.x >> 5;
    float s = 0.f, s2 = 0.f;
    for (int r = rh; r < M_; r += 8) {
        float v = qkv[(size_t)r * C3_ + j0 + jl];
        s += v; s2 += v * v;
    }
    ssum[threadIdx.x] = s; ssq[threadIdx.x] = s2;
    __syncthreads();
    if (threadIdx.x < 32) {
        float S = ssum[threadIdx.x], S2 = ssq[threadIdx.x];
        #pragma unroll
        for (int g = 1; g < 8; g++) {
            S  += ssum[threadIdx.x + 32 * g];
            S2 += ssq [threadIdx.x + 32 * g];
        }
        float mu  = S * (1.0f / (float)M_);
        float var = S2 * (1.0f / (float)M_) - mu * mu;
        g_mu  [j0 + jl] = mu;
        g_rstd[j0 + jl] = rsqrtf(var + 1e-5f);
    }
}

__global__ void norm_spike(const float* __restrict__ qkv,
                           const float* __restrict__ gamma,
                           const float* __restrict__ beta,
                           __nv_bfloat16* __restrict__ outp) {
    const int j = blockIdx.x * 256 + threadIdx.x;
    const size_t row = blockIdx.y;
    const float v = qkv[row * C3_ + j];
    outp[row * C3_ + j] = __float2bfloat16(
        spikef((v - g_mu[j]) * g_rstd[j] * gamma[j] + beta[j]));
}

// ===========================================================================
// HMMA attention. grid (8 q-tiles, 32 bh), 256 threads (8 warps),
// 48KB dyn smem: q@0, k@16384, v@32768, each 128x64 bf16 swizzled
// (row*128 bytes; 16B unit u at phys (u ^ (row&7))).
// Warp w owns q rows 16w..16w+15. S kept in registers; C->A fragment reuse.
// ===========================================================================
__device__ __forceinline__ void load_tile128x64(const __nv_bfloat16* __restrict__ src,
                                                char* dst, int tid) {
    #pragma unroll
    for (int u = 0; u < 4; u++) {
        int i = tid + u * 256;          // 0..1023
        int r = i >> 3;                 // row 0..127
        int cu = i & 7;                 // 16B unit
        uint4 v = *(const uint4*)(src + (size_t)r * C3_ + cu * 8);
        *(uint4*)(dst + r * 128 + ((cu ^ (r & 7)) << 4)) = v;
    }
}

__global__ void __launch_bounds__(256, 1)
attn_hmma(const __nv_bfloat16* __restrict__ sqkv, float* __restrict__ outS) {
    extern __shared__ char sm[];
    const uint32_t smb = smem_u32(sm);
    const int tid = threadIdx.x;
    const int wid = tid >> 5, L = tid & 31;
    const int b = blockIdx.y >> 3, h = blockIdx.y & 7;
    const int n0 = blockIdx.x * 128;
    const __nv_bfloat16* base = sqkv + (size_t)b * N_ * C3_;

    load_tile128x64(base + (size_t)n0 * C3_ + h * HD_, sm, tid);
    __syncthreads();

    // persistent q A-fragments (rows 16*wid .. +15, K=64 -> 4 ksteps)
    uint32_t qa[4][4];
    {
        const int row = 16 * wid + (L & 15);
        const uint32_t rbase = smb + row * 128;
        const int usel = (L >> 4);           // 0/1
        #pragma unroll
        for (int kk = 0; kk < 4; kk++) {
            const int u = 2 * kk + usel;
            ldsm_x4(rbase + ((u ^ (row & 7)) << 4), qa[kk]);
        }
    }

    float oc[8][4] = {};                     // out accum: 8 d-tiles x 4

    for (int mc = 0; mc < N_ / 128; mc++) {
        load_tile128x64(base + (size_t)(mc * 128) * C3_ + C_   + h * HD_, sm + 16384, tid);
        load_tile128x64(base + (size_t)(mc * 128) * C3_ + 2*C_ + h * HD_, sm + 32768, tid);
        __syncthreads();

        // ---- S = q @ k^T : 16 n-tiles of 8 keys ----
        float sc[16][4] = {};
        {
            const int key = (L >> 4) * 8 + (L & 7);   // within 16-key group
            const int us  = (L >> 3) & 1;
            #pragma unroll
            for (int p = 0; p < 8; p++) {
                const int krow = 16 * p + key;
                const uint32_t rb = smb + 16384 + krow * 128;
                #pragma unroll
                for (int kk = 0; kk < 4; kk++) {
                    const int u = 2 * kk + us;
                    uint32_t kb[4];
                    ldsm_x4(rb + ((u ^ (krow & 7)) << 4), kb);
                    mma_bf16(sc[2 * p],     qa[kk], kb[0], kb[1]);
                    mma_bf16(sc[2 * p + 1], qa[kk], kb[2], kb[3]);
                }
            }
        }

        // ---- spike(S) -> bf16 A-fragments (C->A layout identity) ----
        uint32_t ap[8][4];
        #pragma unroll
        for (int j = 0; j < 8; j++) {
            ap[j][0] = pack_bf16x2(spikef(sc[2*j][0]),   spikef(sc[2*j][1]));
            ap[j][1] = pack_bf16x2(spikef(sc[2*j][2]),   spikef(sc[2*j][3]));
            ap[j][2] = pack_bf16x2(spikef(sc[2*j+1][0]), spikef(sc[2*j+1][1]));
            ap[j][3] = pack_bf16x2(spikef(sc[2*j+1][2]), spikef(sc[2*j+1][3]));
        }

        // ---- out += spike(S) @ v ----
        {
            const int key = ((L >> 3) & 1) * 8 + (L & 7);
            const int us  = (L >> 4);
            #pragma unroll
            for (int j = 0; j < 8; j++) {
                const int vrow = 16 * j + key;
                const uint32_t rb = smb + 32768 + vrow * 128;
                #pragma unroll
                for (int dp = 0; dp < 4; dp++) {
                    const int u = 2 * dp + us;
                    uint32_t vb[4];
                    ldsm_x4_t(rb + ((u ^ (vrow & 7)) << 4), vb);
                    mma_bf16(oc[2 * dp],     ap[j], vb[0], vb[1]);
                    mma_bf16(oc[2 * dp + 1], ap[j], vb[2], vb[3]);
                }
            }
        }
        __syncthreads();
    }

    // epilogue: spike(out * 0.125)
    #pragma unroll
    for (int t = 0; t < 8; t++) {
        const int row = n0 + 16 * wid + (L >> 2);
        const int col = h * HD_ + 8 * t + 2 * (L & 3);
        const size_t r0 = (size_t)b * N_ + row;
        float2 v0 = { spikef(oc[t][0] * 0.125f), spikef(oc[t][1] * 0.125f) };
        float2 v1 = { spikef(oc[t][2] * 0.125f), spikef(oc[t][3] * 0.125f) };
        *(float2*)(outS + r0 * C_ + col)       = v0;
        *(float2*)(outS + (r0 + 8) * C_ + col) = v1;
    }
}

// ===========================================================================
extern "C" void kernel_launch(void* const* d_in, const int* in_sizes, int n_in,
                              void* d_out, int out_size) {
    const float* x     = (const float*)d_in[0];
    const float* Wqkv  = (const float*)d_in[1];
    const float* gamma = (const float*)d_in[2];
    const float* beta  = (const float*)d_in[3];
    const float* Wproj = (const float*)d_in[4];
    const float* bproj = (const float*)d_in[5];
    float* out = (float*)d_out;

    float *p_qkv, *p_outs;
    __nv_bfloat16* p_sqkv;
    cudaGetSymbolAddress((void**)&p_qkv,  g_qkv);
    cudaGetSymbolAddress((void**)&p_sqkv, g_sqkv);
    cudaGetSymbolAddress((void**)&p_outs, g_outs);

    cudaFuncSetAttribute(gemm_tf32<true, false>,
                         cudaFuncAttributeMaxDynamicSharedMemorySize, GEMM_SMEM);
    cudaFuncSetAttribute(gemm_tf32<false, true>,
                         cudaFuncAttributeMaxDynamicSharedMemorySize, GEMM_SMEM);
    cudaFuncSetAttribute(attn_hmma,
                         cudaFuncAttributeMaxDynamicSharedMemorySize, 49152);

    // 1) qkv = spike(x) @ Wqkv^T  (tf32 split)
    gemm_tf32<true, false><<<dim3(C3_ / 128, M_ / 128), 256, GEMM_SMEM>>>(
        x, Wqkv, nullptr, p_qkv, M_, C3_, C_);

    // 2) BN stats
    bn_stats<<<C3_ / 32, 256>>>(p_qkv);

    // 3) normalize + spike -> bf16
    norm_spike<<<dim3(C3_ / 256, M_), 256>>>(p_qkv, gamma, beta, p_sqkv);

    // 4) HMMA attention
    attn_hmma<<<dim3(N_ / 128, B_ * H_), 256, 49152>>>(p_sqkv, p_outs);

    // 5) final = out_s @ Wproj^T + bproj  (tf32 split)
    gemm_tf32<false, true><<<dim3(C_ / 128, M_ / 128), 256, GEMM_SMEM>>>(
        p_outs, Wproj, bproj, out, M_, C_, C_);
}

// round 14
// speedup vs baseline: 1.0103x; 1.0103x over previous
#include <cuda_runtime.h>
#include <cuda_bf16.h>
#include <cstdint>

// ---------------------------------------------------------------------------
// Spiking attention, B=4, N=1024, C=512, H=8, hd=64.
//   1) qkv = spike(x) @ Wqkv^T      tf32 HMMA, W split hi/lo (~fp32 accurate)
//   2) BN stats
//   3) s_qkv = spike(BN(qkv)) -> bf16 (exact integers {0..4})
//   4) attention: bf16 HMMA (m16n8k16), exact integer arithmetic
//   5) final = out_s @ Wproj^T + b  tf32 HMMA, W split hi/lo
// ---------------------------------------------------------------------------

#define B_  4
#define N_  1024
#define C_  512
#define H_  8
#define HD_ 64
#define M_  (B_ * N_)      // 4096
#define C3_ (3 * C_)       // 1536

__device__ __forceinline__ float spikef(float x) {
    x = fminf(fmaxf(x, 0.0f), 4.0f);
    return floorf(x + 0.5f);
}

// ---- scratch (allocation-free: device globals) ----
__device__ float          g_qkv [M_ * C3_];
__device__ __nv_bfloat16  g_sqkv[M_ * C3_];
__device__ float          g_mu  [C3_];
__device__ float          g_rstd[C3_];
__device__ float          g_outs[M_ * C_];

// ===========================================================================
// helpers
// ===========================================================================
__device__ __forceinline__ uint32_t smem_u32(const void* p) {
    uint32_t a;
    asm("{ .reg .u64 t; cvta.to.shared.u64 t, %1; cvt.u32.u64 %0, t; }" : "=r"(a) : "l"(p));
    return a;
}
__device__ __forceinline__ uint32_t f2tf32(float f) {
    uint32_t u;
    asm("cvt.rna.tf32.f32 %0, %1;" : "=r"(u) : "f"(f));
    return u;
}
__device__ __forceinline__ void ldsm_x4(uint32_t addr, uint32_t r[4]) {
    asm volatile("ldmatrix.sync.aligned.m8n8.x4.shared.b16 {%0,%1,%2,%3}, [%4];"
                 : "=r"(r[0]), "=r"(r[1]), "=r"(r[2]), "=r"(r[3]) : "r"(addr));
}
__device__ __forceinline__ void ldsm_x4_t(uint32_t addr, uint32_t r[4]) {
    asm volatile("ldmatrix.sync.aligned.m8n8.x4.trans.shared.b16 {%0,%1,%2,%3}, [%4];"
                 : "=r"(r[0]), "=r"(r[1]), "=r"(r[2]), "=r"(r[3]) : "r"(addr));
}
__device__ __forceinline__ void mma_bf16(float c[4], const uint32_t a[4],
                                         uint32_t b0, uint32_t b1) {
    asm volatile("mma.sync.aligned.m16n8k16.row.col.f32.bf16.bf16.f32 "
                 "{%0,%1,%2,%3}, {%4,%5,%6,%7}, {%8,%9}, {%0,%1,%2,%3};"
                 : "+f"(c[0]), "+f"(c[1]), "+f"(c[2]), "+f"(c[3])
                 : "r"(a[0]), "r"(a[1]), "r"(a[2]), "r"(a[3]), "r"(b0), "r"(b1));
}
__device__ __forceinline__ void mma_tf32(float c[4], const uint32_t a[4],
                                         uint32_t b0, uint32_t b1) {
    asm volatile("mma.sync.aligned.m16n8k8.row.col.f32.tf32.tf32.f32 "
                 "{%0,%1,%2,%3}, {%4,%5,%6,%7}, {%8,%9}, {%0,%1,%2,%3};"
                 : "+f"(c[0]), "+f"(c[1]), "+f"(c[2]), "+f"(c[3])
                 : "r"(a[0]), "r"(a[1]), "r"(a[2]), "r"(a[3]), "r"(b0), "r"(b1));
}
__device__ __forceinline__ uint32_t pack_bf16x2(float lo, float hi) {
    uint32_t r;
    asm("cvt.rn.bf16x2.f32 %0, %1, %2;" : "=r"(r) : "f"(hi), "f"(lo));
    return r;
}

// ===========================================================================
// tf32 GEMM with split-W: C[M,N] = cvt(op(A))[M,K] @ (Whi+Wlo)[N,K]^T (+bias)
// 256 threads, tile 128m x 128n, BK=32; warps: 2m x 4n, each 64m x 32n.
// SMEM stride 36 words -> conflict-free fragment lds.
// ===========================================================================
#define GEMM_SMEM (3 * 4608 * 4)   // As, Bhi, Blo: each 128*36 u32

template<bool SPIKE_A, bool HAS_BIAS>
__global__ void __launch_bounds__(256)
gemm_tf32(const float* __restrict__ A, const float* __restrict__ W,
          const float* __restrict__ bias, float* __restrict__ Cm,
          int M, int N, int K) {
    extern __shared__ uint32_t smu[];
    uint32_t* As = smu;           // [128][36]
    uint32_t* Bh = smu + 4608;
    uint32_t* Bl = smu + 9216;
    const int m0 = blockIdx.y * 128;
    const int n0 = blockIdx.x * 128;
    const int tid = threadIdx.x;
    const int wid = tid >> 5, L = tid & 31;
    const int mb = (wid >> 2) * 64;      // warp m base (0/64)
    const int nb = (wid & 3) * 32;       // warp n base
    const int lr = L >> 2, lc = L & 3;

    float c[4][4][4] = {};               // [mtile][ntile][frag]

    for (int k0 = 0; k0 < K; k0 += 32) {
        #pragma unroll
        for (int u = 0; u < 4; u++) {
            int idx = tid + u * 256;     // float4 slot 0..1023
            int r = idx >> 3;
            int cc = (idx & 7) * 4;
            float4 v = *(const float4*)(A + (size_t)(m0 + r) * K + k0 + cc);
            if (SPIKE_A) { v.x = spikef(v.x); v.y = spikef(v.y); v.z = spikef(v.z); v.w = spikef(v.w); }
            uint4 o = { f2tf32(v.x), f2tf32(v.y), f2tf32(v.z), f2tf32(v.w) };
            *(uint4*)(As + r * 36 + cc) = o;

            float4 w = *(const float4*)(W + (size_t)(n0 + r) * K + k0 + cc);
            uint4 hi, lo;
            hi.x = f2tf32(w.x); lo.x = f2tf32(w.x - __uint_as_float(hi.x));
            hi.y = f2tf32(w.y); lo.y = f2tf32(w.y - __uint_as_float(hi.y));
            hi.z = f2tf32(w.z); lo.z = f2tf32(w.z - __uint_as_float(hi.z));
            hi.w = f2tf32(w.w); lo.w = f2tf32(w.w - __uint_as_float(hi.w));
            *(uint4*)(Bh + r * 36 + cc) = hi;
            *(uint4*)(Bl + r * 36 + cc) = lo;
        }
        __syncthreads();

        #pragma unroll
        for (int kk = 0; kk < 4; kk++) {
            const int co = kk * 8 + lc;
            uint32_t af[4][4];
            #pragma unroll
            for (int i = 0; i < 4; i++) {
                const int r = mb + 16 * i + lr;
                af[i][0] = As[r * 36 + co];
                af[i][1] = As[(r + 8) * 36 + co];
                af[i][2] = As[r * 36 + co + 4];
                af[i][3] = As[(r + 8) * 36 + co + 4];
            }
            #pragma unroll
            for (int t = 0; t < 4; t++) {
                const int rn = nb + 8 * t + lr;
                uint32_t bh0 = Bh[rn * 36 + co], bh1 = Bh[rn * 36 + co + 4];
                uint32_t bl0 = Bl[rn * 36 + co], bl1 = Bl[rn * 36 + co + 4];
                #pragma unroll
                for (int i = 0; i < 4; i++) {
                    mma_tf32(c[i][t], af[i], bh0, bh1);
                    mma_tf32(c[i][t], af[i], bl0, bl1);
                }
            }
        }
        __syncthreads();
    }

    #pragma unroll
    for (int i = 0; i < 4; i++) {
        #pragma unroll
        for (int t = 0; t < 4; t++) {
            const int row = m0 + mb + 16 * i + lr;
            const int col = n0 + nb + 8 * t + 2 * lc;
            float b0 = 0.f, b1 = 0.f;
            if (HAS_BIAS) { b0 = bias[col]; b1 = bias[col + 1]; }
            float2 v0 = { c[i][t][0] + b0, c[i][t][1] + b1 };
            float2 v1 = { c[i][t][2] + b0, c[i][t][3] + b1 };
            *(float2*)(Cm + (size_t)row * N + col)       = v0;
            *(float2*)(Cm + (size_t)(row + 8) * N + col) = v1;
        }
    }
}

// ===========================================================================
__global__ void bn_stats(const float* __restrict__ qkv) {
    __shared__ float ssum[256], ssq[256];
    const int j0 = blockIdx.x * 32;
    const int jl = threadIdx.x & 31;
    const int rh = threadIdx.x >> 5;
    float s = 0.f, s2 = 0.f;
    for (int r = rh; r < M_; r += 8) {
        float v = qkv[(size_t)r * C3_ + j0 + jl];
        s += v; s2 += v * v;
    }
    ssum[threadIdx.x] = s; ssq[threadIdx.x] = s2;
    __syncthreads();
    if (threadIdx.x < 32) {
        float S = ssum[threadIdx.x], S2 = ssq[threadIdx.x];
        #pragma unroll
        for (int g = 1; g < 8; g++) {
            S  += ssum[threadIdx.x + 32 * g];
            S2 += ssq [threadIdx.x + 32 * g];
        }
        float mu  = S * (1.0f / (float)M_);
        float var = S2 * (1.0f / (float)M_) - mu * mu;
        g_mu  [j0 + jl] = mu;
        g_rstd[j0 + jl] = rsqrtf(var + 1e-5f);
    }
}

__global__ void norm_spike(const float* __restrict__ qkv,
                           const float* __restrict__ gamma,
                           const float* __restrict__ beta,
                           __nv_bfloat16* __restrict__ outp) {
    const int j = blockIdx.x * 256 + threadIdx.x;
    const size_t row = blockIdx.y;
    const float v = qkv[row * C3_ + j];
    outp[row * C3_ + j] = __float2bfloat16(
        spikef((v - g_mu[j]) * g_rstd[j] * gamma[j] + beta[j]));
}

// ===========================================================================
// HMMA attention. grid (8 q-tiles, 32 bh), 256 threads (8 warps),
// 48KB dyn smem: q@0, k@16384, v@32768, each 128x64 bf16 swizzled
// (row*128 bytes; 16B unit u at phys (u ^ (row&7))).
// Warp w owns q rows 16w..16w+15. S kept in registers; C->A fragment reuse.
// ===========================================================================
__device__ __forceinline__ void load_tile128x64(const __nv_bfloat16* __restrict__ src,
                                                char* dst, int tid) {
    #pragma unroll
    for (int u = 0; u < 4; u++) {
        int i = tid + u * 256;          // 0..1023
        int r = i >> 3;                 // row 0..127
        int cu = i & 7;                 // 16B unit
        uint4 v = *(const uint4*)(src + (size_t)r * C3_ + cu * 8);
        *(uint4*)(dst + r * 128 + ((cu ^ (r & 7)) << 4)) = v;
    }
}

__global__ void __launch_bounds__(256, 1)
attn_hmma(const __nv_bfloat16* __restrict__ sqkv, float* __restrict__ outS) {
    extern __shared__ char sm[];
    const uint32_t smb = smem_u32(sm);
    const int tid = threadIdx.x;
    const int wid = tid >> 5, L = tid & 31;
    const int b = blockIdx.y >> 3, h = blockIdx.y & 7;
    const int n0 = blockIdx.x * 128;
    const __nv_bfloat16* base = sqkv + (size_t)b * N_ * C3_;

    load_tile128x64(base + (size_t)n0 * C3_ + h * HD_, sm, tid);
    __syncthreads();

    // persistent q A-fragments (rows 16*wid .. +15, K=64 -> 4 ksteps)
    uint32_t qa[4][4];
    {
        const int row = 16 * wid + (L & 15);
        const uint32_t rbase = smb + row * 128;
        const int usel = (L >> 4);           // 0/1
        #pragma unroll
        for (int kk = 0; kk < 4; kk++) {
            const int u = 2 * kk + usel;
            ldsm_x4(rbase + ((u ^ (row & 7)) << 4), qa[kk]);
        }
    }

    float oc[8][4] = {};                     // out accum: 8 d-tiles x 4

    for (int mc = 0; mc < N_ / 128; mc++) {
        load_tile128x64(base + (size_t)(mc * 128) * C3_ + C_   + h * HD_, sm + 16384, tid);
        load_tile128x64(base + (size_t)(mc * 128) * C3_ + 2*C_ + h * HD_, sm + 32768, tid);
        __syncthreads();

        // ---- S = q @ k^T : 16 n-tiles of 8 keys ----
        float sc[16][4] = {};
        {
            const int key = (L >> 4) * 8 + (L & 7);   // within 16-key group
            const int us  = (L >> 3) & 1;
            #pragma unroll
            for (int p = 0; p < 8; p++) {
                const int krow = 16 * p + key;
                const uint32_t rb = smb + 16384 + krow * 128;
                #pragma unroll
                for (int kk = 0; kk < 4; kk++) {
                    const int u = 2 * kk + us;
                    uint32_t kb[4];
                    ldsm_x4(rb + ((u ^ (krow & 7)) << 4), kb);
                    mma_bf16(sc[2 * p],     qa[kk], kb[0], kb[1]);
                    mma_bf16(sc[2 * p + 1], qa[kk], kb[2], kb[3]);
                }
            }
        }

        // ---- spike(S) -> bf16 A-fragments (C->A layout identity) ----
        uint32_t ap[8][4];
        #pragma unroll
        for (int j = 0; j < 8; j++) {
            ap[j][0] = pack_bf16x2(spikef(sc[2*j][0]),   spikef(sc[2*j][1]));
            ap[j][1] = pack_bf16x2(spikef(sc[2*j][2]),   spikef(sc[2*j][3]));
            ap[j][2] = pack_bf16x2(spikef(sc[2*j+1][0]), spikef(sc[2*j+1][1]));
            ap[j][3] = pack_bf16x2(spikef(sc[2*j+1][2]), spikef(sc[2*j+1][3]));
        }

        // ---- out += spike(S) @ v ----
        {
            const int key = ((L >> 3) & 1) * 8 + (L & 7);
            const int us  = (L >> 4);
            #pragma unroll
            for (int j = 0; j < 8; j++) {
                const int vrow = 16 * j + key;
                const uint32_t rb = smb + 32768 + vrow * 128;
                #pragma unroll
                for (int dp = 0; dp < 4; dp++) {
                    const int u = 2 * dp + us;
                    uint32_t vb[4];
                    ldsm_x4_t(rb + ((u ^ (vrow & 7)) << 4), vb);
                    mma_bf16(oc[2 * dp],     ap[j], vb[0], vb[1]);
                    mma_bf16(oc[2 * dp + 1], ap[j], vb[2], vb[3]);
                }
            }
        }
        __syncthreads();
    }

    // epilogue: spike(out * 0.125)
    #pragma unroll
    for (int t = 0; t < 8; t++) {
        const int row = n0 + 16 * wid + (L >> 2);
        const int col = h * HD_ + 8 * t + 2 * (L & 3);
        const size_t r0 = (size_t)b * N_ + row;
        float2 v0 = { spikef(oc[t][0] * 0.125f), spikef(oc[t][1] * 0.125f) };
        float2 v1 = { spikef(oc[t][2] * 0.125f), spikef(oc[t][3] * 0.125f) };
        *(float2*)(outS + r0 * C_ + col)       = v0;
        *(float2*)(outS + (r0 + 8) * C_ + col) = v1;
    }
}

// ===========================================================================
extern "C" void kernel_launch(void* const* d_in, const int* in_sizes, int n_in,
                              void* d_out, int out_size) {
    const float* x     = (const float*)d_in[0];
    const float* Wqkv  = (const float*)d_in[1];
    const float* gamma = (const float*)d_in[2];
    const float* beta  = (const float*)d_in[3];
    const float* Wproj = (const float*)d_in[4];
    const float* bproj = (const float*)d_in[5];
    float* out = (float*)d_out;

    float *p_qkv, *p_outs;
    __nv_bfloat16* p_sqkv;
    cudaGetSymbolAddress((void**)&p_qkv,  g_qkv);
    cudaGetSymbolAddress((void**)&p_sqkv, g_sqkv);
    cudaGetSymbolAddress((void**)&p_outs, g_outs);

    cudaFuncSetAttribute(gemm_tf32<true, false>,
                         cudaFuncAttributeMaxDynamicSharedMemorySize, GEMM_SMEM);
    cudaFuncSetAttribute(gemm_tf32<false, true>,
                         cudaFuncAttributeMaxDynamicSharedMemorySize, GEMM_SMEM);
    cudaFuncSetAttribute(attn_hmma,
                         cudaFuncAttributeMaxDynamicSharedMemorySize, 49152);

    // 1) qkv = spike(x) @ Wqkv^T  (tf32 split)
    gemm_tf32<true, false><<<dim3(C3_ / 128, M_ / 128), 256, GEMM_SMEM>>>(
        x, Wqkv, nullptr, p_qkv, M_, C3_, C_);

    // 2) BN stats
    bn_stats<<<C3_ / 32, 256>>>(p_qkv);

    // 3) normalize + spike -> bf16
    norm_spike<<<dim3(C3_ / 256, M_), 256>>>(p_qkv, gamma, beta, p_sqkv);

    // 4) HMMA attention
    attn_hmma<<<dim3(N_ / 128, B_ * H_), 256, 49152>>>(p_sqkv, p_outs);

    // 5) final = out_s @ Wproj^T + bproj  (tf32 split)
    gemm_tf32<false, true><<<dim3(C_ / 128, M_ / 128), 256, GEMM_SMEM>>>(
        p_outs, Wproj, bproj, out, M_, C_, C_);
}

// round 15
// speedup vs baseline: 1.0122x; 1.0019x over previous
#include <cuda_runtime.h>
#include <cuda_bf16.h>
#include <cstdint>

// ---------------------------------------------------------------------------
// Spiking attention, B=4, N=1024, C=512, H=8, hd=64.
//   1) qkv = spike(x) @ Wqkv^T      tf32 HMMA, W split hi/lo (~fp32 accurate)
//   2) BN stats
//   3) s_qkv = spike(BN(qkv)) -> bf16 (exact integers {0..4})
//   4) attention: bf16 HMMA (m16n8k16), exact integer arithmetic
//   5) final = out_s @ Wproj^T + b  tf32 HMMA, W split hi/lo
// ---------------------------------------------------------------------------

#define B_  4
#define N_  1024
#define C_  512
#define H_  8
#define HD_ 64
#define M_  (B_ * N_)      // 4096
#define C3_ (3 * C_)       // 1536

__device__ __forceinline__ float spikef(float x) {
    x = fminf(fmaxf(x, 0.0f), 4.0f);
    return floorf(x + 0.5f);
}

// ---- scratch (allocation-free: device globals) ----
__device__ float          g_qkv [M_ * C3_];
__device__ __nv_bfloat16  g_sqkv[M_ * C3_];
__device__ float          g_mu  [C3_];
__device__ float          g_rstd[C3_];
__device__ float          g_outs[M_ * C_];

// ===========================================================================
// helpers
// ===========================================================================
__device__ __forceinline__ uint32_t smem_u32(const void* p) {
    uint32_t a;
    asm("{ .reg .u64 t; cvta.to.shared.u64 t, %1; cvt.u32.u64 %0, t; }" : "=r"(a) : "l"(p));
    return a;
}
__device__ __forceinline__ uint32_t f2tf32(float f) {
    uint32_t u;
    asm("cvt.rna.tf32.f32 %0, %1;" : "=r"(u) : "f"(f));
    return u;
}
__device__ __forceinline__ void ldsm_x4(uint32_t addr, uint32_t r[4]) {
    asm volatile("ldmatrix.sync.aligned.m8n8.x4.shared.b16 {%0,%1,%2,%3}, [%4];"
                 : "=r"(r[0]), "=r"(r[1]), "=r"(r[2]), "=r"(r[3]) : "r"(addr));
}
__device__ __forceinline__ void ldsm_x4_t(uint32_t addr, uint32_t r[4]) {
    asm volatile("ldmatrix.sync.aligned.m8n8.x4.trans.shared.b16 {%0,%1,%2,%3}, [%4];"
                 : "=r"(r[0]), "=r"(r[1]), "=r"(r[2]), "=r"(r[3]) : "r"(addr));
}
__device__ __forceinline__ void mma_bf16(float c[4], const uint32_t a[4],
                                         uint32_t b0, uint32_t b1) {
    asm volatile("mma.sync.aligned.m16n8k16.row.col.f32.bf16.bf16.f32 "
                 "{%0,%1,%2,%3}, {%4,%5,%6,%7}, {%8,%9}, {%0,%1,%2,%3};"
                 : "+f"(c[0]), "+f"(c[1]), "+f"(c[2]), "+f"(c[3])
                 : "r"(a[0]), "r"(a[1]), "r"(a[2]), "r"(a[3]), "r"(b0), "r"(b1));
}
__device__ __forceinline__ void mma_tf32(float c[4], const uint32_t a[4],
                                         uint32_t b0, uint32_t b1) {
    asm volatile("mma.sync.aligned.m16n8k8.row.col.f32.tf32.tf32.f32 "
                 "{%0,%1,%2,%3}, {%4,%5,%6,%7}, {%8,%9}, {%0,%1,%2,%3};"
                 : "+f"(c[0]), "+f"(c[1]), "+f"(c[2]), "+f"(c[3])
                 : "r"(a[0]), "r"(a[1]), "r"(a[2]), "r"(a[3]), "r"(b0), "r"(b1));
}
__device__ __forceinline__ uint32_t pack_bf16x2(float lo, float hi) {
    uint32_t r;
    asm("cvt.rn.bf16x2.f32 %0, %1, %2;" : "=r"(r) : "f"(hi), "f"(lo));
    return r;
}

// ===========================================================================
// tf32 GEMM with split-W: C[M,N] = cvt(op(A))[M,K] @ (Whi+Wlo)[N,K]^T (+bias)
// 256 threads, tile 128m x 128n, BK=32; warps: 2m x 4n, each 64m x 32n.
// SMEM stride 36 words -> conflict-free fragment lds.
// ===========================================================================
#define GEMM_SMEM (3 * 4608 * 4)   // As, Bhi, Blo: each 128*36 u32

template<bool SPIKE_A, bool HAS_BIAS>
__global__ void __launch_bounds__(256)
gemm_tf32(const float* __restrict__ A, const float* __restrict__ W,
          const float* __restrict__ bias, float* __restrict__ Cm,
          int M, int N, int K) {
    extern __shared__ uint32_t smu[];
    uint32_t* As = smu;           // [128][36]
    uint32_t* Bh = smu + 4608;
    uint32_t* Bl = smu + 9216;
    const int m0 = blockIdx.y * 128;
    const int n0 = blockIdx.x * 128;
    const int tid = threadIdx.x;
    const int wid = tid >> 5, L = tid & 31;
    const int mb = (wid >> 2) * 64;      // warp m base (0/64)
    const int nb = (wid & 3) * 32;       // warp n base
    const int lr = L >> 2, lc = L & 3;

    float c[4][4][4] = {};               // [mtile][ntile][frag]

    for (int k0 = 0; k0 < K; k0 += 32) {
        #pragma unroll
        for (int u = 0; u < 4; u++) {
            int idx = tid + u * 256;     // float4 slot 0..1023
            int r = idx >> 3;
            int cc = (idx & 7) * 4;
            float4 v = *(const float4*)(A + (size_t)(m0 + r) * K + k0 + cc);
            if (SPIKE_A) { v.x = spikef(v.x); v.y = spikef(v.y); v.z = spikef(v.z); v.w = spikef(v.w); }
            uint4 o = { f2tf32(v.x), f2tf32(v.y), f2tf32(v.z), f2tf32(v.w) };
            *(uint4*)(As + r * 36 + cc) = o;

            float4 w = *(const float4*)(W + (size_t)(n0 + r) * K + k0 + cc);
            uint4 hi, lo;
            hi.x = f2tf32(w.x); lo.x = f2tf32(w.x - __uint_as_float(hi.x));
            hi.y = f2tf32(w.y); lo.y = f2tf32(w.y - __uint_as_float(hi.y));
            hi.z = f2tf32(w.z); lo.z = f2tf32(w.z - __uint_as_float(hi.z));
            hi.w = f2tf32(w.w); lo.w = f2tf32(w.w - __uint_as_float(hi.w));
            *(uint4*)(Bh + r * 36 + cc) = hi;
            *(uint4*)(Bl + r * 36 + cc) = lo;
        }
        __syncthreads();

        #pragma unroll
        for (int kk = 0; kk < 4; kk++) {
            const int co = kk * 8 + lc;
            uint32_t af[4][4];
            #pragma unroll
            for (int i = 0; i < 4; i++) {
                const int r = mb + 16 * i + lr;
                af[i][0] = As[r * 36 + co];
                af[i][1] = As[(r + 8) * 36 + co];
                af[i][2] = As[r * 36 + co + 4];
                af[i][3] = As[(r + 8) * 36 + co + 4];
            }
            #pragma unroll
            for (int t = 0; t < 4; t++) {
                const int rn = nb + 8 * t + lr;
                uint32_t bh0 = Bh[rn * 36 + co], bh1 = Bh[rn * 36 + co + 4];
                uint32_t bl0 = Bl[rn * 36 + co], bl1 = Bl[rn * 36 + co + 4];
                #pragma unroll
                for (int i = 0; i < 4; i++) {
                    mma_tf32(c[i][t], af[i], bh0, bh1);
                    mma_tf32(c[i][t], af[i], bl0, bl1);
                }
            }
        }
        __syncthreads();
    }

    #pragma unroll
    for (int i = 0; i < 4; i++) {
        #pragma unroll
        for (int t = 0; t < 4; t++) {
            const int row = m0 + mb + 16 * i + lr;
            const int col = n0 + nb + 8 * t + 2 * lc;
            float b0 = 0.f, b1 = 0.f;
            if (HAS_BIAS) { b0 = bias[col]; b1 = bias[col + 1]; }
            float2 v0 = { c[i][t][0] + b0, c[i][t][1] + b1 };
            float2 v1 = { c[i][t][2] + b0, c[i][t][3] + b1 };
            *(float2*)(Cm + (size_t)row * N + col)       = v0;
            *(float2*)(Cm + (size_t)(row + 8) * N + col) = v1;
        }
    }
}

// ===========================================================================
__global__ void bn_stats(const float* __restrict__ qkv) {
    __shared__ float ssum[256], ssq[256];
    const int j0 = blockIdx.x * 32;
    const int jl = threadIdx.x & 31;
    const int rh = threadIdx.x >> 5;
    float s = 0.f, s2 = 0.f;
    for (int r = rh; r < M_; r += 8) {
        float v = qkv[(size_t)r * C3_ + j0 + jl];
        s += v; s2 += v * v;
    }
    ssum[threadIdx.x] = s; ssq[threadIdx.x] = s2;
    __syncthreads();
    if (threadIdx.x < 32) {
        float S = ssum[threadIdx.x], S2 = ssq[threadIdx.x];
        #pragma unroll
        for (int g = 1; g < 8; g++) {
            S  += ssum[threadIdx.x + 32 * g];
            S2 += ssq [threadIdx.x + 32 * g];
        }
        float mu  = S * (1.0f / (float)M_);
        float var = S2 * (1.0f / (float)M_) - mu * mu;
        g_mu  [j0 + jl] = mu;
        g_rstd[j0 + jl] = rsqrtf(var + 1e-5f);
    }
}

__global__ void norm_spike(const float* __restrict__ qkv,
                           const float* __restrict__ gamma,
                           const float* __restrict__ beta,
                           __nv_bfloat16* __restrict__ outp) {
    const int j = blockIdx.x * 256 + threadIdx.x;
    const size_t row = blockIdx.y;
    const float v = qkv[row * C3_ + j];
    outp[row * C3_ + j] = __float2bfloat16(
        spikef((v - g_mu[j]) * g_rstd[j] * gamma[j] + beta[j]));
}

// ===========================================================================
// HMMA attention. grid (8 q-tiles, 32 bh), 256 threads (8 warps),
// 48KB dyn smem: q@0, k@16384, v@32768, each 128x64 bf16 swizzled
// (row*128 bytes; 16B unit u at phys (u ^ (row&7))).
// Warp w owns q rows 16w..16w+15. S kept in registers; C->A fragment reuse.
// ===========================================================================
__device__ __forceinline__ void load_tile128x64(const __nv_bfloat16* __restrict__ src,
                                                char* dst, int tid) {
    #pragma unroll
    for (int u = 0; u < 4; u++) {
        int i = tid + u * 256;          // 0..1023
        int r = i >> 3;                 // row 0..127
        int cu = i & 7;                 // 16B unit
        uint4 v = *(const uint4*)(src + (size_t)r * C3_ + cu * 8);
        *(uint4*)(dst + r * 128 + ((cu ^ (r & 7)) << 4)) = v;
    }
}

__global__ void __launch_bounds__(256, 1)
attn_hmma(const __nv_bfloat16* __restrict__ sqkv, float* __restrict__ outS) {
    extern __shared__ char sm[];
    const uint32_t smb = smem_u32(sm);
    const int tid = threadIdx.x;
    const int wid = tid >> 5, L = tid & 31;
    const int b = blockIdx.y >> 3, h = blockIdx.y & 7;
    const int n0 = blockIdx.x * 128;
    const __nv_bfloat16* base = sqkv + (size_t)b * N_ * C3_;

    load_tile128x64(base + (size_t)n0 * C3_ + h * HD_, sm, tid);
    __syncthreads();

    // persistent q A-fragments (rows 16*wid .. +15, K=64 -> 4 ksteps)
    uint32_t qa[4][4];
    {
        const int row = 16 * wid + (L & 15);
        const uint32_t rbase = smb + row * 128;
        const int usel = (L >> 4);           // 0/1
        #pragma unroll
        for (int kk = 0; kk < 4; kk++) {
            const int u = 2 * kk + usel;
            ldsm_x4(rbase + ((u ^ (row & 7)) << 4), qa[kk]);
        }
    }

    float oc[8][4] = {};                     // out accum: 8 d-tiles x 4

    for (int mc = 0; mc < N_ / 128; mc++) {
        load_tile128x64(base + (size_t)(mc * 128) * C3_ + C_   + h * HD_, sm + 16384, tid);
        load_tile128x64(base + (size_t)(mc * 128) * C3_ + 2*C_ + h * HD_, sm + 32768, tid);
        __syncthreads();

        // ---- S = q @ k^T : 16 n-tiles of 8 keys ----
        float sc[16][4] = {};
        {
            const int key = (L >> 4) * 8 + (L & 7);   // within 16-key group
            const int us  = (L >> 3) & 1;
            #pragma unroll
            for (int p = 0; p < 8; p++) {
                const int krow = 16 * p + key;
                const uint32_t rb = smb + 16384 + krow * 128;
                #pragma unroll
                for (int kk = 0; kk < 4; kk++) {
                    const int u = 2 * kk + us;
                    uint32_t kb[4];
                    ldsm_x4(rb + ((u ^ (krow & 7)) << 4), kb);
                    mma_bf16(sc[2 * p],     qa[kk], kb[0], kb[1]);
                    mma_bf16(sc[2 * p + 1], qa[kk], kb[2], kb[3]);
                }
            }
        }

        // ---- spike(S) -> bf16 A-fragments (C->A layout identity) ----
        uint32_t ap[8][4];
        #pragma unroll
        for (int j = 0; j < 8; j++) {
            ap[j][0] = pack_bf16x2(spikef(sc[2*j][0]),   spikef(sc[2*j][1]));
            ap[j][1] = pack_bf16x2(spikef(sc[2*j][2]),   spikef(sc[2*j][3]));
            ap[j][2] = pack_bf16x2(spikef(sc[2*j+1][0]), spikef(sc[2*j+1][1]));
            ap[j][3] = pack_bf16x2(spikef(sc[2*j+1][2]), spikef(sc[2*j+1][3]));
        }

        // ---- out += spike(S) @ v ----
        {
            const int key = ((L >> 3) & 1) * 8 + (L & 7);
            const int us  = (L >> 4);
            #pragma unroll
            for (int j = 0; j < 8; j++) {
                const int vrow = 16 * j + key;
                const uint32_t rb = smb + 32768 + vrow * 128;
                #pragma unroll
                for (int dp = 0; dp < 4; dp++) {
                    const int u = 2 * dp + us;
                    uint32_t vb[4];
                    ldsm_x4_t(rb + ((u ^ (vrow & 7)) << 4), vb);
                    mma_bf16(oc[2 * dp],     ap[j], vb[0], vb[1]);
                    mma_bf16(oc[2 * dp + 1], ap[j], vb[2], vb[3]);
                }
            }
        }
        __syncthreads();
    }

    // epilogue: spike(out * 0.125)
    #pragma unroll
    for (int t = 0; t < 8; t++) {
        const int row = n0 + 16 * wid + (L >> 2);
        const int col = h * HD_ + 8 * t + 2 * (L & 3);
        const size_t r0 = (size_t)b * N_ + row;
        float2 v0 = { spikef(oc[t][0] * 0.125f), spikef(oc[t][1] * 0.125f) };
        float2 v1 = { spikef(oc[t][2] * 0.125f), spikef(oc[t][3] * 0.125f) };
        *(float2*)(outS + r0 * C_ + col)       = v0;
        *(float2*)(outS + (r0 + 8) * C_ + col) = v1;
    }
}

// ===========================================================================
extern "C" void kernel_launch(void* const* d_in, const int* in_sizes, int n_in,
                              void* d_out, int out_size) {
    const float* x     = (const float*)d_in[0];
    const float* Wqkv  = (const float*)d_in[1];
    const float* gamma = (const float*)d_in[2];
    const float* beta  = (const float*)d_in[3];
    const float* Wproj = (const float*)d_in[4];
    const float* bproj = (const float*)d_in[5];
    float* out = (float*)d_out;

    float *p_qkv, *p_outs;
    __nv_bfloat16* p_sqkv;
    cudaGetSymbolAddress((void**)&p_qkv,  g_qkv);
    cudaGetSymbolAddress((void**)&p_sqkv, g_sqkv);
    cudaGetSymbolAddress((void**)&p_outs, g_outs);

    cudaFuncSetAttribute(gemm_tf32<true, false>,
                         cudaFuncAttributeMaxDynamicSharedMemorySize, GEMM_SMEM);
    cudaFuncSetAttribute(gemm_tf32<false, true>,
                         cudaFuncAttributeMaxDynamicSharedMemorySize, GEMM_SMEM);
    cudaFuncSetAttribute(attn_hmma,
                         cudaFuncAttributeMaxDynamicSharedMemorySize, 49152);

    // 1) qkv = spike(x) @ Wqkv^T  (tf32 split)
    gemm_tf32<true, false><<<dim3(C3_ / 128, M_ / 128), 256, GEMM_SMEM>>>(
        x, Wqkv, nullptr, p_qkv, M_, C3_, C_);

    // 2) BN stats
    bn_stats<<<C3_ / 32, 256>>>(p_qkv);

    // 3) normalize + spike -> bf16
    norm_spike<<<dim3(C3_ / 256, M_), 256>>>(p_qkv, gamma, beta, p_sqkv);

    // 4) HMMA attention
    attn_hmma<<<dim3(N_ / 128, B_ * H_), 256, 49152>>>(p_sqkv, p_outs);

    // 5) final = out_s @ Wproj^T + bproj  (tf32 split)
    gemm_tf32<false, true><<<dim3(C_ / 128, M_ / 128), 256, GEMM_SMEM>>>(
        p_outs, Wproj, bproj, out, M_, C_, C_);
}